// round 1
// baseline (speedup 1.0000x reference)
#include <cuda_runtime.h>
#include <stdint.h>

#define H 2048
#define W 2048
#define NB 16
#define KS 11
#define PS 10
#define PAD 5
#define HO 205                 // conv output: floor((2048+10-11)/10)+1
#define OUT 2255               // 205 * (PS+1)
#define CELLS (HO*HO)
#define OUT_TOTAL (3*OUT*OUT)

// Intermediate per-cell result: [3][HO][HO]
__device__ float g_mid[3 * HO * HO];

// ---------------------------------------------------------------------------
// Kernel 1: one warp per output cell.
// Computes the 16-bin histogram of the 11x11 window, finds argmax bin
// (first-max tie-break, matching jnp.argmax), then per-channel mean of
// pixels belonging to that bin.
// ---------------------------------------------------------------------------
__global__ void __launch_bounds__(256) cell_kernel(const float* __restrict__ rgb) {
    const int warp_id = (blockIdx.x * blockDim.x + threadIdx.x) >> 5;
    const int lane = threadIdx.x & 31;
    if (warp_id >= CELLS) return;

    const int oh = warp_id / HO;
    const int ow = warp_id - oh * HO;
    const int y0 = oh * PS - PAD;
    const int x0 = ow * PS - PAD;

    const float* __restrict__ rp = rgb;
    const float* __restrict__ gp = rgb + H * W;
    const float* __restrict__ bp = rgb + 2 * H * W;

    float rv[4], gv[4], bv[4];
    int bn[4];
    unsigned long long hlo = 0ULL, hhi = 0ULL; // bins 0-7 / 8-15, 8-bit counters

#pragma unroll
    for (int t = 0; t < 4; t++) {
        const int p = lane + t * 32;
        bn[t] = -1; rv[t] = 0.f; gv[t] = 0.f; bv[t] = 0.f;
        if (p < KS * KS) {
            const int dy = p / KS;
            const int dx = p - dy * KS;
            const int y = y0 + dy;
            const int x = x0 + dx;
            if ((unsigned)y < (unsigned)H && (unsigned)x < (unsigned)W) {
                const int off = y * W + x;
                const float r = __ldg(rp + off);
                const float g = __ldg(gp + off);
                const float b = __ldg(bp + off);
                rv[t] = r; gv[t] = g; bv[t] = b;
                // mean/256*16 == mean * 2^-4 exactly; IEEE ops to match XLA
                const float m = __fdiv_rn(__fadd_rn(__fadd_rn(r, g), b), 3.0f);
                int bi = (int)(m * 0.0625f);
                bi = bi < 0 ? 0 : (bi > 15 ? 15 : bi);
                bn[t] = bi;
                const unsigned long long inc = 1ULL << ((bi & 7) * 8);
                if (bi < 8) hlo += inc; else hhi += inc;
            }
        }
    }

    // Warp-reduce packed histograms (counters never exceed 121 < 256)
#pragma unroll
    for (int s = 16; s > 0; s >>= 1) {
        hlo += __shfl_xor_sync(0xffffffffu, hlo, s);
        hhi += __shfl_xor_sync(0xffffffffu, hhi, s);
    }

    // Argmax (ascending scan, strict '>' keeps first max like jnp.argmax)
    int amax = 0, cmax = -1;
#pragma unroll
    for (int b = 0; b < 16; b++) {
        const unsigned long long h = (b < 8) ? hlo : hhi;
        const int c = (int)((h >> ((b & 7) * 8)) & 0xFFULL);
        if (c > cmax) { cmax = c; amax = b; }
    }

    // Masked per-channel sums of pixels in the argmax bin
    float sr = 0.f, sg = 0.f, sb = 0.f;
#pragma unroll
    for (int t = 0; t < 4; t++) {
        if (bn[t] == amax) { sr += rv[t]; sg += gv[t]; sb += bv[t]; }
    }
#pragma unroll
    for (int s = 16; s > 0; s >>= 1) {
        sr += __shfl_xor_sync(0xffffffffu, sr, s);
        sg += __shfl_xor_sync(0xffffffffu, sg, s);
        sb += __shfl_xor_sync(0xffffffffu, sb, s);
    }

    if (lane == 0) {
        const float cm = (float)cmax;
        const int idx = oh * HO + ow;
        g_mid[idx]              = __fdiv_rn(sr, cm);
        g_mid[idx + HO * HO]    = __fdiv_rn(sg, cm);
        g_mid[idx + 2 * HO * HO]= __fdiv_rn(sb, cm);
    }
}

// ---------------------------------------------------------------------------
// Kernel 2: upsample 205x205 -> 2255x2255 per channel.
// Each 11x11 output block = 10x10 replicated value + zero pad row/col.
// One thread per output element, fully coalesced stores.
// ---------------------------------------------------------------------------
__global__ void __launch_bounds__(256) upsample_kernel(float* __restrict__ out) {
    const unsigned i = blockIdx.x * blockDim.x + threadIdx.x;
    if (i >= (unsigned)OUT_TOTAL) return;

    const unsigned plane = (unsigned)(OUT * OUT);
    const unsigned c = i / plane;
    const unsigned rem = i - c * plane;
    const unsigned y = rem / (unsigned)OUT;
    const unsigned x = rem - y * (unsigned)OUT;

    const unsigned oh = y / 11u;
    const unsigned ii = y - oh * 11u;
    const unsigned ocw = x / 11u;
    const unsigned jj = x - ocw * 11u;

    float v = 0.0f;
    if (ii < 10u && jj < 10u) {
        v = g_mid[c * HO * HO + oh * HO + ocw];
    }
    out[i] = v;
}

extern "C" void kernel_launch(void* const* d_in, const int* in_sizes, int n_in,
                              void* d_out, int out_size) {
    const float* rgb = (const float*)d_in[0];
    float* out = (float*)d_out;

    // Kernel 1: one warp per cell, 8 warps per block
    const int blocks1 = (CELLS + 7) / 8;
    cell_kernel<<<blocks1, 256>>>(rgb);

    // Kernel 2: one thread per output element
    const int blocks2 = (OUT_TOTAL + 255) / 256;
    upsample_kernel<<<blocks2, 256>>>(out);
}

// round 2
// speedup vs baseline: 1.4399x; 1.4399x over previous
#include <cuda_runtime.h>
#include <stdint.h>

#define H 2048
#define W 2048
#define NB 16
#define KS 11
#define PS 10
#define PAD 5
#define HO 205                 // conv output: floor((2048+10-11)/10)+1
#define OUT 2255               // 205 * (PS+1)
#define CELLS (HO*HO)
#define ROWS_TOTAL (3*OUT)

// Intermediate per-cell result: [3][HO][HO]
__device__ float g_mid[3 * HO * HO];

// ---------------------------------------------------------------------------
// Kernel 1: one warp per output cell.
// 16-bin histogram of the 11x11 window (packed 8-bit counters, carry-free),
// argmax bin (first-max tie-break like jnp.argmax), per-channel mean of
// pixels in that bin.
// ---------------------------------------------------------------------------
__global__ void __launch_bounds__(256) cell_kernel(const float* __restrict__ rgb) {
    const int warp_id = (blockIdx.x * blockDim.x + threadIdx.x) >> 5;
    const int lane = threadIdx.x & 31;
    if (warp_id >= CELLS) return;

    const int oh = warp_id / HO;
    const int ow = warp_id - oh * HO;
    const int y0 = oh * PS - PAD;
    const int x0 = ow * PS - PAD;

    const float* __restrict__ rp = rgb;
    const float* __restrict__ gp = rgb + H * W;
    const float* __restrict__ bp = rgb + 2 * H * W;

    float rv[4], gv[4], bv[4];
    int bn[4];
    unsigned long long hlo = 0ULL, hhi = 0ULL; // bins 0-7 / 8-15, 8-bit counters

#pragma unroll
    for (int t = 0; t < 4; t++) {
        const int p = lane + t * 32;
        bn[t] = -1; rv[t] = 0.f; gv[t] = 0.f; bv[t] = 0.f;
        if (p < KS * KS) {
            const int dy = p / KS;
            const int dx = p - dy * KS;
            const int y = y0 + dy;
            const int x = x0 + dx;
            if ((unsigned)y < (unsigned)H && (unsigned)x < (unsigned)W) {
                const int off = y * W + x;
                const float r = __ldg(rp + off);
                const float g = __ldg(gp + off);
                const float b = __ldg(bp + off);
                rv[t] = r; gv[t] = g; bv[t] = b;
                // mean/256*16 == mean * 2^-4 exactly; IEEE ops to match XLA
                const float m = __fdiv_rn(__fadd_rn(__fadd_rn(r, g), b), 3.0f);
                int bi = (int)(m * 0.0625f);
                bi = bi < 0 ? 0 : (bi > 15 ? 15 : bi);
                bn[t] = bi;
                const unsigned long long inc = 1ULL << ((bi & 7) * 8);
                if (bi < 8) hlo += inc; else hhi += inc;
            }
        }
    }

    // Warp-reduce packed histograms via redux.sync (carry-free: per-bin
    // totals <= 121 < 256, so byte lanes never overflow).
    unsigned h0 = __reduce_add_sync(0xffffffffu, (unsigned)hlo);
    unsigned h1 = __reduce_add_sync(0xffffffffu, (unsigned)(hlo >> 32));
    unsigned h2 = __reduce_add_sync(0xffffffffu, (unsigned)hhi);
    unsigned h3 = __reduce_add_sync(0xffffffffu, (unsigned)(hhi >> 32));

    // Argmax (ascending scan, strict '>' keeps first max like jnp.argmax)
    int amax = 0, cmax = -1;
#pragma unroll
    for (int b = 0; b < 16; b++) {
        const unsigned hw = (b < 4) ? h0 : (b < 8) ? h1 : (b < 12) ? h2 : h3;
        const int c = (int)((hw >> ((b & 3) * 8)) & 0xFFu);
        if (c > cmax) { cmax = c; amax = b; }
    }

    // Masked per-channel sums of pixels in the argmax bin
    float sr = 0.f, sg = 0.f, sb = 0.f;
#pragma unroll
    for (int t = 0; t < 4; t++) {
        if (bn[t] == amax) { sr += rv[t]; sg += gv[t]; sb += bv[t]; }
    }
#pragma unroll
    for (int s = 16; s > 0; s >>= 1) {
        sr += __shfl_xor_sync(0xffffffffu, sr, s);
        sg += __shfl_xor_sync(0xffffffffu, sg, s);
        sb += __shfl_xor_sync(0xffffffffu, sb, s);
    }

    if (lane == 0) {
        const float cm = (float)cmax;
        const int idx = oh * HO + ow;
        g_mid[idx]               = __fdiv_rn(sr, cm);
        g_mid[idx + HO * HO]     = __fdiv_rn(sg, cm);
        g_mid[idx + 2 * HO * HO] = __fdiv_rn(sb, cm);
    }
}

// ---------------------------------------------------------------------------
// Kernel 2: upsample 205x205 -> 2255x2255 per channel.
// One block per output row (c,y). Each thread writes a float4, tracking
// (ow, jj) incrementally so only ONE division per 4 outputs.
// Row base alignment handled with scalar head/tail.
// ---------------------------------------------------------------------------
__global__ void __launch_bounds__(256) upsample_kernel(float* __restrict__ out) {
    const int row = blockIdx.x;          // 0 .. 3*2255-1
    const int c = row / OUT;
    const int y = row - c * OUT;
    const int oh = y / 11;
    const int ii = y - oh * 11;
    const bool live = (ii < 10);

    const float* __restrict__ midc = g_mid + c * HO * HO + oh * HO;
    float* __restrict__ orow = out + (size_t)row * OUT;

    // Alignment of row start within 16B: (row*OUT) mod 4 floats
    const int mis = (int)(((unsigned)row * (unsigned)OUT) & 3u);
    const int head = (4 - mis) & 3;
    const int nv = (OUT - head) >> 2;            // number of full float4
    const int tail_start = head + nv * 4;
    const int ntail = OUT - tail_start;          // 0..3

    // Scalar head
    if ((int)threadIdx.x < head) {
        const int x = threadIdx.x;
        const int o = x / 11;
        const int j = x - o * 11;
        orow[x] = (live && j < 10) ? midc[o] : 0.0f;
    }
    // Scalar tail
    if ((int)threadIdx.x >= 4 && (int)threadIdx.x < 4 + ntail) {
        const int x = tail_start + (threadIdx.x - 4);
        const int o = x / 11;
        const int j = x - o * 11;
        orow[x] = (live && j < 10) ? midc[o] : 0.0f;
    }

    // Vector body
    for (int v4 = threadIdx.x; v4 < nv; v4 += blockDim.x) {
        const int x = head + v4 * 4;
        int ow = x / 11;
        int jj = x - ow * 11;
        float cv = live ? midc[ow] : 0.0f;
        float4 o;
        float* po = &o.x;
#pragma unroll
        for (int k = 0; k < 4; k++) {
            po[k] = (jj < 10) ? cv : 0.0f;
            jj++;
            if (k < 3 && jj == 11) {       // k<3: compile-time, avoids OOB read
                jj = 0; ow++;
                cv = live ? midc[ow] : 0.0f;
            }
        }
        *(float4*)(orow + x) = o;
    }
}

extern "C" void kernel_launch(void* const* d_in, const int* in_sizes, int n_in,
                              void* d_out, int out_size) {
    const float* rgb = (const float*)d_in[0];
    float* out = (float*)d_out;

    // Kernel 1: one warp per cell, 8 warps per block
    const int blocks1 = (CELLS + 7) / 8;
    cell_kernel<<<blocks1, 256>>>(rgb);

    // Kernel 2: one block per output row
    upsample_kernel<<<ROWS_TOTAL, 256>>>(out);
}

// round 3
// speedup vs baseline: 1.4470x; 1.0049x over previous
#include <cuda_runtime.h>
#include <stdint.h>

#define H 2048
#define W 2048
#define KS 11
#define PS 10
#define PAD 5
#define HO 205                 // conv output: floor((2048+10-11)/10)+1
#define OUT 2255               // 205 * (PS+1)
#define CELLS (HO*HO)
#define UP_BLOCKS (3*HO)       // one block per (channel, oh)

// Intermediate per-cell result: [3][HO][HO]
__device__ float g_mid[3 * HO * HO];

// ---------------------------------------------------------------------------
// Kernel 1: one warp per output cell.
// 16-bin histogram of the 11x11 window (packed 8-bit counters), argmax bin
// via single warp-reduce-max (first-max tie-break like jnp.argmax),
// per-channel mean of pixels in that bin.
// ---------------------------------------------------------------------------
__global__ void __launch_bounds__(256) cell_kernel(const float* __restrict__ rgb,
                                                   int base, int limit) {
    const int wid = base + ((blockIdx.x * blockDim.x + threadIdx.x) >> 5);
    if (wid >= limit) return;
    const int lane = threadIdx.x & 31;

    const int oh = wid / HO;
    const int ow = wid - oh * HO;
    const int y0 = oh * PS - PAD;
    const int x0 = ow * PS - PAD;
    const bool interior = (oh > 0) & (ow > 0);   // lower bounds only; upper always OK

    const float* __restrict__ rp = rgb;
    const float* __restrict__ gp = rgb + H * W;
    const float* __restrict__ bp = rgb + 2 * H * W;

    int off[4];
    bool act[4];
#pragma unroll
    for (int t = 0; t < 4; t++) {
        const int p = lane + t * 32;
        const int dy = p / KS;
        const int dx = p - dy * KS;
        const int y = y0 + dy;
        const int x = x0 + dx;
        bool a = (p < KS * KS);
        if (!interior) a = a && (y >= 0) && (x >= 0);
        act[t] = a;
        off[t] = y * W + x;
    }

    // Batch all loads first (max MLP)
    float rv[4], gv[4], bv[4];
#pragma unroll
    for (int t = 0; t < 4; t++) rv[t] = act[t] ? __ldg(rp + off[t]) : 0.0f;
#pragma unroll
    for (int t = 0; t < 4; t++) gv[t] = act[t] ? __ldg(gp + off[t]) : 0.0f;
#pragma unroll
    for (int t = 0; t < 4; t++) bv[t] = act[t] ? __ldg(bp + off[t]) : 0.0f;

    // Bin + packed histogram (bins 0-7 in hlo, 8-15 in hhi; 8-bit counters,
    // per-bin totals <= 121 < 256 so reduction is carry-free)
    int bn[4];
    unsigned long long hlo = 0ULL, hhi = 0ULL;
#pragma unroll
    for (int t = 0; t < 4; t++) {
        // mean/256*16 == mean * 2^-4 exactly; IEEE ops to match XLA
        const float m = __fdiv_rn(__fadd_rn(__fadd_rn(rv[t], gv[t]), bv[t]), 3.0f);
        const int bi = (int)(m * 0.0625f);   // inputs in [0,255): bi in [0,15]
        bn[t] = bi;
        if (act[t]) {
            const unsigned long long inc = 1ULL << ((bi & 7) * 8);
            if (bi < 8) hlo += inc; else hhi += inc;
        }
    }

    const unsigned h0 = __reduce_add_sync(0xffffffffu, (unsigned)hlo);
    const unsigned h1 = __reduce_add_sync(0xffffffffu, (unsigned)(hlo >> 32));
    const unsigned h2 = __reduce_add_sync(0xffffffffu, (unsigned)hhi);
    const unsigned h3 = __reduce_add_sync(0xffffffffu, (unsigned)(hhi >> 32));

    // Lane-parallel argmax: lane (b = lane&15) owns bin b.
    // key = (cnt<<4) | (15-b): ties -> larger 15-b -> smaller bin wins,
    // matching jnp.argmax first-max semantics.
    const int b = lane & 15;
    const unsigned hw = (b < 8) ? ((b < 4) ? h0 : h1) : ((b < 12) ? h2 : h3);
    const unsigned cnt = (hw >> ((b & 3) * 8)) & 0xFFu;
    const unsigned key = (cnt << 4) | (unsigned)(15 - b);
    const unsigned kmax = __reduce_max_sync(0xffffffffu, key);
    const int amax = 15 - (int)(kmax & 15u);
    const float cm = (float)(kmax >> 4);

    // Masked per-channel sums (inactive slots hold 0.0 so no act check needed)
    float sr = 0.f, sg = 0.f, sb = 0.f;
#pragma unroll
    for (int t = 0; t < 4; t++) {
        if (bn[t] == amax) { sr += rv[t]; sg += gv[t]; sb += bv[t]; }
    }
#pragma unroll
    for (int s = 16; s > 0; s >>= 1) {
        sr += __shfl_xor_sync(0xffffffffu, sr, s);
        sg += __shfl_xor_sync(0xffffffffu, sg, s);
        sb += __shfl_xor_sync(0xffffffffu, sb, s);
    }

    if (lane == 0) {
        g_mid[wid]               = __fdiv_rn(sr, cm);
        g_mid[wid + HO * HO]     = __fdiv_rn(sg, cm);
        g_mid[wid + 2 * HO * HO] = __fdiv_rn(sb, cm);
    }
}

// ---------------------------------------------------------------------------
// Kernel 2: upsample 205x205 -> 2255x2255 per channel.
// One block per (c, oh). Build the expanded row template once in smem
// (4 byte-shift copies so every row alignment gets aligned LDS.128),
// then copy it to the 10 live rows and zero-fill the pad row.
// ---------------------------------------------------------------------------
__global__ void __launch_bounds__(256) upsample_kernel(float* __restrict__ out,
                                                       int base) {
    const int blk = base + blockIdx.x;   // 0 .. 3*205-1
    const int c = blk / HO;
    const int oh = blk - c * HO;
    const int tid = threadIdx.x;

    __shared__ __align__(16) float s[4][2256];

    const float* __restrict__ midc = g_mid + c * HO * HO + oh * HO;

    // Build template row: srow[x] = (x%11 < 10) ? mid[x/11] : 0
    for (int x = tid; x < OUT; x += 256) {
        const int o = x / 11;
        const int j = x - o * 11;
        s[0][x] = (j < 10) ? midc[o] : 0.0f;
    }
    __syncthreads();
    // Shifted copies: s[a][i] = s[0][a+i]
    for (int x = tid; x < OUT; x += 256) {
        const float v = s[0][x];
        if (x >= 1) s[1][x - 1] = v;
        if (x >= 2) s[2][x - 2] = v;
        if (x >= 3) s[3][x - 3] = v;
    }
    __syncthreads();

    const size_t row0 = (size_t)c * OUT + (size_t)oh * 11;
    for (int r = 0; r < 11; r++) {
        const size_t ri = row0 + r;
        float* __restrict__ orow = out + ri * OUT;
        const int h = (int)((4u - (unsigned)((ri * OUT) & 3)) & 3u);
        const int nv = (OUT - h) >> 2;
        const int nt = (OUT - h) & 3;

        if (r < 10) {
            if (tid < h) orow[tid] = s[0][tid];
            if (tid >= 4 && tid < 4 + nt) {
                const int x = h + nv * 4 + (tid - 4);
                orow[x] = s[0][x];
            }
            const float4* __restrict__ sv = (const float4*)s[h];
            float4* __restrict__ ov = (float4*)(orow + h);
            for (int v = tid; v < nv; v += 256) ov[v] = sv[v];
        } else {
            if (tid < h) orow[tid] = 0.0f;
            if (tid >= 4 && tid < 4 + nt) orow[h + nv * 4 + (tid - 4)] = 0.0f;
            const float4 z = make_float4(0.f, 0.f, 0.f, 0.f);
            float4* __restrict__ ov = (float4*)(orow + h);
            for (int v = tid; v < nv; v += 256) ov[v] = z;
        }
    }
}

extern "C" void kernel_launch(void* const* d_in, const int* in_sizes, int n_in,
                              void* d_out, int out_size) {
    const float* rgb = (const float*)d_in[0];
    float* out = (float*)d_out;

    // Cell kernel split in two halves (also makes ncu -s5 -c1 land on cellB)
    const int half = CELLS / 2;                       // 21012
    const int blocksA = (half + 7) / 8;
    const int blocksB = ((CELLS - half) + 7) / 8;
    cell_kernel<<<blocksA, 256>>>(rgb, 0, half);
    cell_kernel<<<blocksB, 256>>>(rgb, half, CELLS);

    // Upsample split in two halves
    const int uhalf = UP_BLOCKS / 2;                  // 307
    upsample_kernel<<<uhalf, 256>>>(out, 0);
    upsample_kernel<<<UP_BLOCKS - uhalf, 256>>>(out, uhalf);
}

// round 4
// speedup vs baseline: 2.2516x; 1.5560x over previous
#include <cuda_runtime.h>
#include <stdint.h>

#define H 2048
#define W 2048
#define KS 11
#define PS 10
#define PAD 5
#define HO 205                 // conv output: floor((2048+10-11)/10)+1
#define OUT 2255               // 205 * (PS+1)
#define CELLS (HO*HO)
#define ROWS_TOTAL (3*OUT)

// Intermediate per-cell result: [3][HO][HO]
__device__ float g_mid[3 * HO * HO];

// ---------------------------------------------------------------------------
// Kernel 1: one warp per output cell.
// 16-bin histogram of the 11x11 window (packed 8-bit counters), argmax bin
// via single warp-reduce-max (first-max tie-break like jnp.argmax),
// per-channel mean of pixels in that bin.
// ---------------------------------------------------------------------------
__global__ void __launch_bounds__(256) cell_kernel(const float* __restrict__ rgb) {
    const int wid = (blockIdx.x * blockDim.x + threadIdx.x) >> 5;
    if (wid >= CELLS) return;
    const int lane = threadIdx.x & 31;

    const int oh = wid / HO;
    const int ow = wid - oh * HO;
    const int y0 = oh * PS - PAD;
    const int x0 = ow * PS - PAD;

    const float* __restrict__ rp = rgb;
    const float* __restrict__ gp = rgb + H * W;
    const float* __restrict__ bp = rgb + 2 * H * W;

    // p = lane + 32t; window is 121 px: t=0..2 always active, t=3 iff lane<25.
    int off[4];
    bool act[4];
    act[0] = true; act[1] = true; act[2] = true; act[3] = (lane < 25);
#pragma unroll
    for (int t = 0; t < 4; t++) {
        const int p = lane + t * 32;
        const int dy = p / KS;
        const int dx = p - dy * KS;
        off[t] = (y0 + dy) * W + (x0 + dx);
    }
    if ((oh == 0) | (ow == 0)) {   // border cells: 409 of 42025
#pragma unroll
        for (int t = 0; t < 4; t++) {
            const int p = lane + t * 32;
            const int dy = p / KS;
            const int dx = p - dy * KS;
            act[t] = act[t] && (y0 + dy >= 0) && (x0 + dx >= 0);
        }
    }

    // Batch all loads first (max MLP); inactive slots hold 0.
    float rv[4], gv[4], bv[4];
#pragma unroll
    for (int t = 0; t < 4; t++) rv[t] = act[t] ? __ldg(rp + off[t]) : 0.0f;
#pragma unroll
    for (int t = 0; t < 4; t++) gv[t] = act[t] ? __ldg(gp + off[t]) : 0.0f;
#pragma unroll
    for (int t = 0; t < 4; t++) bv[t] = act[t] ? __ldg(bp + off[t]) : 0.0f;

    // Bin + packed histogram (bins 0-7 in hlo, 8-15 in hhi; 8-bit counters,
    // per-bin totals <= 121 < 256 so the warp reduction is carry-free)
    int bn[4];
    unsigned long long hlo = 0ULL, hhi = 0ULL;
#pragma unroll
    for (int t = 0; t < 4; t++) {
        // bin = floor(mean(r,g,b)/256*16) = floor((r+g+b)*(1/3)*2^-4)
        const float s = __fadd_rn(__fadd_rn(rv[t], gv[t]), bv[t]);
        const float m = __fmul_rn(s, 0.3333333432674408f);   // 1/3 rn
        const int bi = (int)(__fmul_rn(m, 0.0625f));          // in [0,15]
        bn[t] = bi;
        if (act[t]) {
            const unsigned long long inc = 1ULL << ((bi & 7) * 8);
            if (bi < 8) hlo += inc; else hhi += inc;
        }
    }

    const unsigned h0 = __reduce_add_sync(0xffffffffu, (unsigned)hlo);
    const unsigned h1 = __reduce_add_sync(0xffffffffu, (unsigned)(hlo >> 32));
    const unsigned h2 = __reduce_add_sync(0xffffffffu, (unsigned)hhi);
    const unsigned h3 = __reduce_add_sync(0xffffffffu, (unsigned)(hhi >> 32));

    // Lane-parallel argmax: lane (b = lane&15) owns bin b.
    // key = (cnt<<4) | (15-b): ties -> larger 15-b -> smaller bin wins,
    // matching jnp.argmax first-max semantics.
    const int b = lane & 15;
    const unsigned hw = (b < 8) ? ((b < 4) ? h0 : h1) : ((b < 12) ? h2 : h3);
    const unsigned cnt = (hw >> ((b & 3) * 8)) & 0xFFu;
    const unsigned key = (cnt << 4) | (unsigned)(15 - b);
    const unsigned kmax = __reduce_max_sync(0xffffffffu, key);
    const int amax = 15 - (int)(kmax & 15u);
    const float cm = (float)(kmax >> 4);

    // Masked per-channel sums (inactive slots hold 0.0)
    float sr = 0.f, sg = 0.f, sb = 0.f;
#pragma unroll
    for (int t = 0; t < 4; t++) {
        if (bn[t] == amax) { sr += rv[t]; sg += gv[t]; sb += bv[t]; }
    }
#pragma unroll
    for (int s = 16; s > 0; s >>= 1) {
        sr += __shfl_xor_sync(0xffffffffu, sr, s);
        sg += __shfl_xor_sync(0xffffffffu, sg, s);
        sb += __shfl_xor_sync(0xffffffffu, sb, s);
    }

    if (lane == 0) {
        g_mid[wid]               = __fdiv_rn(sr, cm);
        g_mid[wid + HO * HO]     = __fdiv_rn(sg, cm);
        g_mid[wid + 2 * HO * HO] = __fdiv_rn(sb, cm);
    }
}

// ---------------------------------------------------------------------------
// Kernel 2: upsample 205x205 -> 2255x2255 per channel.
// One block per output row: branch-free magic-div indexing, L1-hot mid-row
// gathers, aligned float4 stores. Pad rows are pure zero fill.
// ---------------------------------------------------------------------------
__global__ void __launch_bounds__(128) upsample_kernel(float* __restrict__ out) {
    const int row = blockIdx.x;            // 0 .. 3*2255-1
    const int tid = threadIdx.x;
    const unsigned ur = (unsigned)row;
    const unsigned c = ur / (unsigned)OUT;
    const unsigned y = ur - c * (unsigned)OUT;
    const unsigned oh = y / 11u;
    const unsigned ii = y - oh * 11u;

    float* __restrict__ orow = out + (size_t)row * OUT;
    const int h = (int)((4u - ((ur * (unsigned)OUT) & 3u)) & 3u);
    const int nv = (OUT - h) >> 2;
    const int nt = OUT - h - nv * 4;
    float4* __restrict__ ov = (float4*)(orow + h);

    if (ii == 10u) {                       // pad row: zeros
        if (tid < h) orow[tid] = 0.0f;
        if (tid >= 4 && tid < 4 + nt) orow[h + nv * 4 + (tid - 4)] = 0.0f;
        const float4 z = make_float4(0.f, 0.f, 0.f, 0.f);
        for (int v = tid; v < nv; v += 128) ov[v] = z;
        return;
    }

    const float* __restrict__ midc = g_mid + c * HO * HO + oh * HO;

    // Scalar head (x <= 2: o=0, j=x<10 -> always live)
    if (tid < h) orow[tid] = __ldg(midc);
    // Scalar tail (x in 2252..2254)
    if (tid >= 4 && tid < 4 + nt) {
        const unsigned x = (unsigned)(h + nv * 4 + (tid - 4));
        const unsigned o = x / 11u;
        const unsigned j = x - o * 11u;
        orow[x] = (j < 10u) ? __ldg(midc + o) : 0.0f;
    }

    // Vector body: 4 independent magic-divs per float4, no divergence
    for (int v = tid; v < nv; v += 128) {
        const unsigned x0 = (unsigned)(h + v * 4);
        float4 o;
        float* po = &o.x;
#pragma unroll
        for (int k = 0; k < 4; k++) {
            const unsigned x = x0 + (unsigned)k;
            const unsigned ow = x / 11u;
            const unsigned j = x - ow * 11u;
            po[k] = (j < 10u) ? __ldg(midc + ow) : 0.0f;
        }
        ov[v] = o;
    }
}

extern "C" void kernel_launch(void* const* d_in, const int* in_sizes, int n_in,
                              void* d_out, int out_size) {
    const float* rgb = (const float*)d_in[0];
    float* out = (float*)d_out;

    const int blocks1 = (CELLS + 7) / 8;       // one warp per cell, 8/block
    cell_kernel<<<blocks1, 256>>>(rgb);

    upsample_kernel<<<ROWS_TOTAL, 128>>>(out); // one block per output row
}